// round 17
// baseline (speedup 1.0000x reference)
#include <cuda_runtime.h>
#include <math.h>

// CNF_9663676416569: vector field + exact divergence via weight-precomputed E.
//
// dx  = tanh(tanh([t,x] @ W1 + b1) @ W2 + b2) @ W3 + b3
// div = sum_j (1-h2_j^2) * sum_m (1-h1_m^2) * E[m,j]
//   where E[m,j] = W2[m,j] * sum_k W1[1+k, m] * W3[j, k]   (weights only)
//
// R17: inner-loop LDS count 40 -> 18 per warp-tile:
//   - k-permutation sigma(p) = (p&3)*4 + (p>>2) inside each 16-k tile,
//     applied to h1 storage ([m][k-pos], pitch 528) AND staged B rows, so
//     A fragments (both k-steps) load as 2x LDS.128.
//   - (W2,E) element-interleaved staging buffer -> each (bw,be) fragment
//     pair is one LDS.64; XOR swizzle (word ^= 8*kq) keeps it bank-free.
//   tf32 mma m16n8k8 (Z2 2-pass split-A, U 1-pass), FFMA2 Phase A / DX.

#define Hm 512
#define Dm 64
#define MT 32
#define KP  528         // s_h1m pitch ([m][k-pos])
#define STP 36          // s_st pitch ([col][row])
#define KT  16          // staged k-tile
#define WEP 520         // interleaved (w,e) row pitch (512 + 8)
#define WEBUF (KT * WEP)
#define NTHR 512

typedef unsigned long long ull;
typedef unsigned int u32;

__device__ float g_W2t[Hm * Hm];                // tf32-rounded W2
__device__ float g_Et [Hm * Hm];                // tf32-rounded E
__device__ __align__(16) ull g_W1d[65 * Hm];    // (w,w) pairs for Phase A
__device__ __align__(16) ull g_W3d[Hm * Dm];    // (w,w) pairs for DX

__device__ __forceinline__ ull pack2(float lo, float hi) {
    ull d; asm("mov.b64 %0, {%1, %2};" : "=l"(d) : "f"(lo), "f"(hi)); return d;
}
__device__ __forceinline__ void unpack2(ull v, float& lo, float& hi) {
    asm("mov.b64 {%0, %1}, %2;" : "=f"(lo), "=f"(hi) : "l"(v));
}
__device__ __forceinline__ void ffma2(ull& d, ull a, ull b) {
    asm("fma.rn.f32x2 %0, %1, %2, %0;" : "+l"(d) : "l"(a), "l"(b));
}
__device__ __forceinline__ void fadd2(ull& d, ull a) {
    asm("add.rn.f32x2 %0, %0, %1;" : "+l"(d) : "l"(a));
}
__device__ __forceinline__ u32 f2tf32(float f) {
    u32 r; asm("cvt.rna.tf32.f32 %0, %1;" : "=r"(r) : "f"(f)); return r;
}
__device__ __forceinline__ void mma_tf32(float* d, const u32* a, const u32* b) {
    asm volatile(
        "mma.sync.aligned.m16n8k8.row.col.f32.tf32.tf32.f32 "
        "{%0,%1,%2,%3}, {%4,%5,%6,%7}, {%8,%9}, {%0,%1,%2,%3};\n"
        : "+f"(d[0]), "+f"(d[1]), "+f"(d[2]), "+f"(d[3])
        : "r"(a[0]), "r"(a[1]), "r"(a[2]), "r"(a[3]), "r"(b[0]), "r"(b[1]));
}

// ---------------------------------------------------------------------------
// Precompute: E = W2 .* (W1[1:,:]^T @ W3^T); write tf32-rounded W2/E,
// duplicated W1 (Phase A) and W3 (DX).
// ---------------------------------------------------------------------------
__global__ __launch_bounds__(256)
void compute_E_kernel(const float* __restrict__ W1,
                      const float* __restrict__ W2,
                      const float* __restrict__ W3) {
    __shared__ float As[64][33];
    __shared__ float Bs[32][65];
    const int m0 = blockIdx.x * 32;
    const int j0 = blockIdx.y * 32;
    const int tid = threadIdx.x;

    for (int p = tid; p < 64 * 32; p += 256) {
        int i = p >> 5, ml = p & 31;
        As[i][ml] = W1[(1 + i) * Hm + m0 + ml];
    }
    for (int p = tid; p < 32 * 64; p += 256) {
        int i = p & 63, jl = p >> 6;
        Bs[jl][i] = W3[(j0 + jl) * 64 + i];
    }
    __syncthreads();

    const int jl = tid & 31;
    const int mg = tid >> 5;
    float acc[4] = {0.f, 0.f, 0.f, 0.f};
    #pragma unroll
    for (int i = 0; i < 64; i++) {
        float b = Bs[jl][i];
        #pragma unroll
        for (int q = 0; q < 4; q++)
            acc[q] = fmaf(As[i][mg * 4 + q], b, acc[q]);
    }
    #pragma unroll
    for (int q = 0; q < 4; q++) {
        int m = m0 + mg * 4 + q;
        int j = j0 + jl;
        const float w2 = W2[m * Hm + j];
        g_W2t[m * Hm + j] = __uint_as_float(f2tf32(w2));
        g_Et [m * Hm + j] = __uint_as_float(f2tf32(w2 * acc[q]));
    }

    if (blockIdx.y == 0) {          // dup W1 columns m0..m0+31
        for (int p = tid; p < 65 * 32; p += 256) {
            int c = p >> 5, ml = p & 31;
            const float w = W1[c * Hm + m0 + ml];
            g_W1d[c * Hm + m0 + ml] = pack2(w, w);
        }
    } else if (blockIdx.y == 1) {   // dup W3 rows m0..m0+31
        for (int p = tid; p < 32 * 64; p += 256) {
            int r = p >> 6, cc = p & 63;
            const float w = W3[(m0 + r) * Dm + cc];
            g_W3d[(m0 + r) * Dm + cc] = pack2(w, w);
        }
    }
}

// ---------------------------------------------------------------------------
// Main kernel: one CTA = 32 batch rows, 512 threads (16 warps), 1 CTA/SM.
// SMEM: s_xaT[65][32], s_h1m[32][528] ([m][k-pos], k permuted per 16-tile),
//       s_st[256][36], s_we[2][16][520] interleaved (w,e), s_div[32]
//       = 179.5 KB
// ---------------------------------------------------------------------------
__global__ __launch_bounds__(NTHR, 1)
void cnf_main_kernel(const float* __restrict__ t,
                     const float* __restrict__ x,
                     const float* __restrict__ W1,
                     const float* __restrict__ b1,
                     const float* __restrict__ W2,
                     const float* __restrict__ b2,
                     const float* __restrict__ W3,
                     const float* __restrict__ b3,
                     float* __restrict__ out) {
    extern __shared__ float sm[];
    float* s_xaT = sm;                        // 65*32  = 2080
    float* s_h1m = sm + 65 * 32;              // 32*528 = 16896
    float* s_st  = s_h1m + 32 * KP;           // 256*36 = 9216
    float* s_we  = s_st + 256 * STP;          // 2*16*520 = 16640
    float* s_div = s_we + 2 * WEBUF;          // 32

    const int tid  = threadIdx.x;
    const int row0 = blockIdx.x * MT;

    if (tid < MT) s_div[tid] = 0.f;

    // ---- load [t, x] tile transposed ----
    const float tval = t[0];
    for (int p = tid; p < 65 * 32; p += NTHR) {
        int c = p >> 5, r = p & 31;
        s_xaT[c * 32 + r] = (c == 0) ? tval
                                     : x[(size_t)(row0 + r) * 65 + (c - 1)];
    }
    __syncthreads();

    // ---- Phase A: H1 = tanh(Xa @ W1 + b1); 1 n per thread (FFMA2) ----
    // store at s_h1m[m][(n>>4)*16 + sigma(n&15)], sigma(k)=(k&3)*4+(k>>2)
    {
        const int n = tid;
        const float bb = b1[n];
        const ull pb = pack2(bb, bb);
        ull acc2[16];
        #pragma unroll
        for (int p = 0; p < 16; p++) acc2[p] = pb;
        #pragma unroll 4
        for (int c = 0; c < 65; c++) {
            const ull pw = g_W1d[c * Hm + n];
            const ull* xa = (const ull*)(s_xaT + c * 32);
            #pragma unroll
            for (int p = 0; p < 16; p++) ffma2(acc2[p], xa[p], pw);
        }
        const int col = ((n >> 4) << 4) + ((n & 3) * 4 + ((n >> 2) & 3));
        float* dst = s_h1m + col;
        #pragma unroll
        for (int p = 0; p < 16; p++) {
            float lo, hi; unpack2(acc2[p], lo, hi);
            dst[(2 * p)     * KP] = tanhf(lo);
            dst[(2 * p + 1) * KP] = tanhf(hi);
        }
    }
    __syncthreads();

    // ---- Phase B ----
    const int lane = tid & 31;
    const int wid  = tid >> 5;
    const int g    = lane >> 2;       // fragment row
    const int kq   = lane & 3;        // fragment k
    const int m0   = (wid & 1) * 16;  // warp m-base
    const int nwb  = (wid >> 1) * 32; // warp n-base within chunk (0..224)

    // staging map: warp wid handles storage row wid; lane covers 8 n's
    const int sg_r  = wid;                   // storage row 0..15
    const int sg_lk = ((sg_r & 3) * 4 + (sg_r >> 2));  // logical tile-row
    const int sg_n  = lane * 8;              // n base (8 values)
    const int sg_sw = 8 * (sg_r >> 2);       // XOR swizzle for this row

    // DX map
    const int rp  = tid & 15, cgd = tid >> 4;   // cgd 0..31
    const int r0  = rp * 2;
    const int cgm = cgd & 15;
    const int d3  = cgm * 4;
    const int kk0 = (cgd >> 4) * 128;

    ull accDX[4] = {0ull, 0ull, 0ull, 0ull};
    float dv0 = 0.f, dv1 = 0.f;

    for (int ch = 0; ch < 2; ch++) {
        const int n0 = ch * 256;

        float accZ[4][4], accU[4][4];
        #pragma unroll
        for (int j = 0; j < 4; j++)
            #pragma unroll
            for (int c = 0; c < 4; c++) { accZ[j][c] = 0.f; accU[j][c] = 0.f; }

        const float* __restrict__ srcW = g_W2t + n0 + sg_n;
        const float* __restrict__ srcE = g_Et  + n0 + sg_n;

        // preload + stage tile 0 into buffer 0
        float4 wA, wB, eA, eB;
        {
            const size_t kr = (size_t)sg_lk * Hm;
            wA = *(const float4*)(srcW + kr);
            wB = *(const float4*)(srcW + kr + 4);
            eA = *(const float4*)(srcE + kr);
            eB = *(const float4*)(srcE + kr + 4);
        }
        {
            float* dst = s_we + sg_r * WEP;
            const int cb = 16 * lane;
            *(float4*)(dst + ((cb +  0) ^ sg_sw)) =
                make_float4(wA.x, eA.x, wA.y, eA.y);
            *(float4*)(dst + ((cb +  4) ^ sg_sw)) =
                make_float4(wA.z, eA.z, wA.w, eA.w);
            *(float4*)(dst + ((cb +  8) ^ sg_sw)) =
                make_float4(wB.x, eB.x, wB.y, eB.y);
            *(float4*)(dst + ((cb + 12) ^ sg_sw)) =
                make_float4(wB.z, eB.z, wB.w, eB.w);
        }

        for (int kt = 0; kt < Hm / KT; kt++) {
            // prefetch tile kt+1 (clamped)
            {
                const int ktn = (kt + 1 < Hm / KT) ? (kt + 1) : kt;
                const size_t kr = (size_t)(ktn * KT + sg_lk) * Hm;
                wA = *(const float4*)(srcW + kr);
                wB = *(const float4*)(srcW + kr + 4);
                eA = *(const float4*)(srcE + kr);
                eB = *(const float4*)(srcE + kr + 4);
            }
            __syncthreads();

            const float* buf = s_we + (kt & 1) * WEBUF;

            // A: all raw values for both k-steps in 2 LDS.128
            const float4 aLo =
                *(const float4*)(s_h1m + (m0 + g) * KP + kt * KT + 4 * kq);
            const float4 aHi =
                *(const float4*)(s_h1m + (m0 + g + 8) * KP + kt * KT + 4 * kq);

            const int xw = 8 * kq;

            #pragma unroll
            for (int ks = 0; ks < 2; ks++) {
                const float hv[4] = {
                    ks ? aLo.z : aLo.x,  ks ? aHi.z : aHi.x,
                    ks ? aLo.w : aLo.y,  ks ? aHi.w : aHi.y };
                u32 ah[4], al[4], ag[4];
                #pragma unroll
                for (int i = 0; i < 4; i++) {
                    ah[i] = f2tf32(hv[i]);
                    al[i] = f2tf32(hv[i] - __uint_as_float(ah[i]));
                    ag[i] = f2tf32(fmaf(-hv[i], hv[i], 1.f));
                }

                const int rb = 4 * kq + 2 * ks;     // storage rows rb, rb+1
                #pragma unroll
                for (int j = 0; j < 4; j++) {
                    const int nb2 = 2 * (nwb + j * 8 + g);
                    const float2 we0 =
                        *(const float2*)(buf + rb * WEP + (nb2 ^ xw));
                    const float2 we1 =
                        *(const float2*)(buf + (rb + 1) * WEP + (nb2 ^ xw));
                    u32 bw[2], be[2];
                    bw[0] = __float_as_uint(we0.x);
                    bw[1] = __float_as_uint(we1.x);
                    be[0] = __float_as_uint(we0.y);
                    be[1] = __float_as_uint(we1.y);
                    mma_tf32(accZ[j], ah, bw);
                    mma_tf32(accZ[j], al, bw);
                    mma_tf32(accU[j], ag, be);
                }
            }

            // stage tile kt+1 into the other buffer
            {
                float* dst = s_we + ((kt + 1) & 1) * WEBUF + sg_r * WEP;
                const int cb = 16 * lane;
                *(float4*)(dst + ((cb +  0) ^ sg_sw)) =
                    make_float4(wA.x, eA.x, wA.y, eA.y);
                *(float4*)(dst + ((cb +  4) ^ sg_sw)) =
                    make_float4(wA.z, eA.z, wA.w, eA.w);
                *(float4*)(dst + ((cb +  8) ^ sg_sw)) =
                    make_float4(wB.x, eB.x, wB.y, eB.y);
                *(float4*)(dst + ((cb + 12) ^ sg_sw)) =
                    make_float4(wB.z, eB.z, wB.w, eB.w);
            }
        }

        // ---- chunk epilogue: h2, div partials, stage h2 to s_st ----
        __syncthreads();   // previous s_st readers (DX) done
        #pragma unroll
        for (int j = 0; j < 4; j++) {
            const int col0 = nwb + j * 8 + kq * 2;       // chunk-local
            const float b20 = b2[n0 + col0];
            const float b21 = b2[n0 + col0 + 1];
            const float h00 = tanhf(accZ[j][0] + b20);
            const float h01 = tanhf(accZ[j][1] + b21);
            const float h10 = tanhf(accZ[j][2] + b20);
            const float h11 = tanhf(accZ[j][3] + b21);
            dv0 = fmaf(fmaf(-h00, h00, 1.f), accU[j][0], dv0);
            dv0 = fmaf(fmaf(-h01, h01, 1.f), accU[j][1], dv0);
            dv1 = fmaf(fmaf(-h10, h10, 1.f), accU[j][2], dv1);
            dv1 = fmaf(fmaf(-h11, h11, 1.f), accU[j][3], dv1);
            s_st[col0       * STP + m0 + g]     = h00;
            s_st[(col0 + 1) * STP + m0 + g]     = h01;
            s_st[col0       * STP + m0 + g + 8] = h10;
            s_st[(col0 + 1) * STP + m0 + g + 8] = h11;
        }
        __syncthreads();

        // ---- DX: accDX += h2[:, kk0:+128] @ W3[n0+kk0:+128, d3:+4] ----
        const ulonglong2* __restrict__ pW3 =
            (const ulonglong2*)g_W3d + (d3 >> 1);
        #pragma unroll 8
        for (int kk = 0; kk < 128; kk++) {
            const int kc = kk0 + kk;
            const ull a = *(const ull*)(s_st + kc * STP + r0);
            const ulonglong2 w0 = pW3[(size_t)(n0 + kc) * 32];
            const ulonglong2 w1 = pW3[(size_t)(n0 + kc) * 32 + 1];
            ffma2(accDX[0], a, w0.x); ffma2(accDX[1], a, w0.y);
            ffma2(accDX[2], a, w1.x); ffma2(accDX[3], a, w1.y);
        }
        __syncthreads();
    }

    // ---- DX replica reduction (cgd>=16 adds into cgd<16) ----
    ull* s_red = (ull*)s_st;
    if (cgd >= 16) {
        ull* dst = s_red + ((size_t)(cgm * 16 + rp)) * 4;
        #pragma unroll
        for (int j = 0; j < 4; j++) dst[j] = accDX[j];
    }
    __syncthreads();
    if (cgd < 16) {
        const ull* src = s_red + ((size_t)(cgm * 16 + rp)) * 4;
        #pragma unroll
        for (int j = 0; j < 4; j++) fadd2(accDX[j], src[j]);
    }

    // ---- final epilogue ----
    atomicAdd(&s_div[m0 + g],     dv0);
    atomicAdd(&s_div[m0 + g + 8], dv1);

    if (cgd < 16) {
        const float4 b3v = *(const float4*)(b3 + d3);
        float v[2][4];
        #pragma unroll
        for (int j = 0; j < 4; j++) unpack2(accDX[j], v[0][j], v[1][j]);
        #pragma unroll
        for (int s = 0; s < 2; s++) {
            const size_t ro = (size_t)(row0 + r0 + s) * 65 + d3;
            out[ro + 0] = v[s][0] + b3v.x;
            out[ro + 1] = v[s][1] + b3v.y;
            out[ro + 2] = v[s][2] + b3v.z;
            out[ro + 3] = v[s][3] + b3v.w;
        }
    }
    __syncthreads();
    if (tid < MT)
        out[(size_t)(row0 + tid) * 65 + 64] = s_div[tid];
}

// ---------------------------------------------------------------------------
extern "C" void kernel_launch(void* const* d_in, const int* in_sizes, int n_in,
                              void* d_out, int out_size) {
    const float* t  = (const float*)d_in[0];
    const float* x  = (const float*)d_in[1];
    const float* W1 = (const float*)d_in[2];
    const float* b1 = (const float*)d_in[3];
    const float* W2 = (const float*)d_in[4];
    const float* b2 = (const float*)d_in[5];
    const float* W3 = (const float*)d_in[6];
    const float* b3 = (const float*)d_in[7];
    float* out = (float*)d_out;

    compute_E_kernel<<<dim3(16, 16), 256>>>(W1, W2, W3);

    const int smem_bytes =
        (65 * 32 + 32 * KP + 256 * STP + 2 * WEBUF + 32) * (int)sizeof(float);
    cudaFuncSetAttribute(cnf_main_kernel,
                         cudaFuncAttributeMaxDynamicSharedMemorySize, smem_bytes);
    cnf_main_kernel<<<8192 / MT, NTHR, smem_bytes>>>(t, x, W1, b1, W2, b2,
                                                     W3, b3, out);
}